// round 8
// baseline (speedup 1.0000x reference)
#include <cuda_runtime.h>

static constexpr int BATCH = 8;
static constexpr int SEQ   = 16384;
static constexpr int CH    = 256;
static constexpr int TOPN  = 2048;
static constexpr int ROWS  = BATCH * SEQ;     // 131072
static constexpr int QUADS = ROWS / 4;        // 32768

static constexpr int K1_GRID    = 444;        // 148 SMs * 3 resident CTAs
static constexpr int K1_THREADS = 256;        // 8 warps
static constexpr int K1_WARPS_TOTAL = K1_GRID * (K1_THREADS / 32);  // 3552

__device__ float g_score[ROWS];
__device__ float g_psum[K1_GRID];
__device__ float g_psq[K1_GRID];
__device__ unsigned g_idx[BATCH * TOPN];
__device__ unsigned long long g_keys[ROWS];   // slow-path scratch only
__device__ unsigned g_done   = 0;             // ticket counter (self-resetting)
__device__ unsigned g_passed = 0;             // selector pass counter (self-resetting)

// ---------------------------------------------------------------------------
// K1 + fused select.
// Phase 1 (all 444 CTAs): scores + per-CTA sum/sumsq. A warp covers 4 rows,
// 8 lanes per row; 8 front-batched float4 streaming loads per thread; row
// reduce = 3-step shfl butterfly (4 rows simultaneously in one register).
// Phase 2 (last 8 CTAs by ticket): spin until all partials visible, compute
// mean/var, then per-batch stable compaction of the first TOPN indices with
// normalized score <= 0 (== relu zeros, which lead a stable ascending argsort).
// Counters self-reset so every graph replay starts clean.
// ---------------------------------------------------------------------------
__global__ __launch_bounds__(K1_THREADS, 3) void score_select_kernel(
        const float* __restrict__ x,
        const float* __restrict__ w,
        const float* __restrict__ bias,
        const float* __restrict__ gamma,
        const float* __restrict__ beta) {
    const int tid    = threadIdx.x;
    const int warp   = tid >> 5;
    const int lane   = tid & 31;
    const int subrow = lane >> 3;     // 0..3 : which of the warp's 4 rows
    const int pos    = lane & 7;      // 0..7 : position within the row
    const int gw     = blockIdx.x * (K1_THREADS / 32) + warp;

    const float4* wv = (const float4*)w;
    float4 W[8];
#pragma unroll
    for (int j = 0; j < 8; j++) W[j] = wv[pos + 8*j];   // loop-invariant
    const float bb = bias[0];

    float S = 0.f, Q = 0.f;

    for (int quad = gw; quad < QUADS; quad += K1_WARPS_TOTAL) {
        const size_t row = (size_t)quad * 4 + subrow;
        const float4* xb = (const float4*)(x + row * CH);   // 64 float4 per row

        float4 v[8];
#pragma unroll
        for (int j = 0; j < 8; j++) v[j] = __ldcs(xb + pos + 8*j);

        float d = 0.f;
#pragma unroll
        for (int j = 0; j < 8; j++)
            d += v[j].x*W[j].x + v[j].y*W[j].y + v[j].z*W[j].z + v[j].w*W[j].w;

        d += __shfl_xor_sync(0xffffffffu, d, 4);
        d += __shfl_xor_sync(0xffffffffu, d, 2);
        d += __shfl_xor_sync(0xffffffffu, d, 1);

        if (pos == 0) {                 // lanes 0,8,16,24 -> 4 consecutive rows
            float c = d + bb;
            __stcs(&g_score[row], c);
            S += c;
            Q += c * c;
        }
    }

    // per-CTA reduction of S, Q
#pragma unroll
    for (int off = 16; off > 0; off >>= 1) {
        S += __shfl_xor_sync(0xffffffffu, S, off);
        Q += __shfl_xor_sync(0xffffffffu, Q, off);
    }
    __shared__ float ws[K1_THREADS / 32], wq[K1_THREADS / 32];
    if (lane == 0) { ws[warp] = S; wq[warp] = Q; }
    __syncthreads();
    if (tid < 32) {
        float s = (tid < K1_THREADS / 32) ? ws[tid] : 0.f;
        float q = (tid < K1_THREADS / 32) ? wq[tid] : 0.f;
#pragma unroll
        for (int off = 4; off > 0; off >>= 1) {
            s += __shfl_xor_sync(0xffffffffu, s, off);
            q += __shfl_xor_sync(0xffffffffu, q, off);
        }
        if (tid == 0) { g_psum[blockIdx.x] = s; g_psq[blockIdx.x] = q; }
    }

    // ----- ticket: publish partials, take arrival ticket -----
    __shared__ unsigned ticket_s;
    __syncthreads();
    __threadfence();
    if (tid == 0) ticket_s = atomicAdd(&g_done, 1u);
    __syncthreads();
    const unsigned ticket = ticket_s;
    if (ticket < (unsigned)(K1_GRID - BATCH)) return;   // not a selector

    const int b = (int)ticket - (K1_GRID - BATCH);      // my batch

    // ----- wait for all CTAs' partials & scores -----
    if (tid == 0) {
        while (*(volatile unsigned*)&g_done != (unsigned)K1_GRID) { }
        __threadfence();
        unsigned p = atomicAdd(&g_passed, 1u);
        if (p == (unsigned)(BATCH - 1)) {     // last selector past the barrier:
            atomicExch(&g_done, 0u);          // safe to reset for next replay
            atomicExch(&g_passed, 0u);
        }
    }
    __syncthreads();
    __threadfence();

    // ----- mean / var from all partials -----
    float sS = 0.f, sQ = 0.f;
    for (int i = tid; i < K1_GRID; i += K1_THREADS) { sS += g_psum[i]; sQ += g_psq[i]; }
#pragma unroll
    for (int off = 16; off > 0; off >>= 1) {
        sS += __shfl_xor_sync(0xffffffffu, sS, off);
        sQ += __shfl_xor_sync(0xffffffffu, sQ, off);
    }
    __shared__ float rs[8], rq[8];
    if (lane == 0) { rs[warp] = sS; rq[warp] = sQ; }
    __syncthreads();
    {
        float s = rs[lane & 7], q = rq[lane & 7];
#pragma unroll
        for (int off = 4; off > 0; off >>= 1) {
            s += __shfl_xor_sync(0xffffffffu, s, off);
            q += __shfl_xor_sync(0xffffffffu, q, off);
        }
        rs[0] = s; rq[0] = q;   // benign rewrite, all warps same value path
    }
    __syncthreads();
    float mean = rs[0] / (float)ROWS;
    float var  = rq[0] / (float)ROWS - mean * mean;
    if (var < 0.f) var = 0.f;
    float scale = rsqrtf(var + 1e-5f) * gamma[0];
    float shift = beta[0] - mean * scale;

    // ----- stable compaction: 64 elements per thread -----
    const float* sc = g_score + (size_t)b * SEQ;
    const float4* p4 = (const float4*)(sc + tid * 64);
    unsigned m0 = 0, m1 = 0;
#pragma unroll
    for (int j = 0; j < 8; j++) {
        float4 v = p4[j];
        if (fmaf(v.x, scale, shift) <= 0.f) m0 |= 1u << (4*j + 0);
        if (fmaf(v.y, scale, shift) <= 0.f) m0 |= 1u << (4*j + 1);
        if (fmaf(v.z, scale, shift) <= 0.f) m0 |= 1u << (4*j + 2);
        if (fmaf(v.w, scale, shift) <= 0.f) m0 |= 1u << (4*j + 3);
    }
#pragma unroll
    for (int j = 8; j < 16; j++) {
        float4 v = p4[j];
        if (fmaf(v.x, scale, shift) <= 0.f) m1 |= 1u << (4*j - 32);
        if (fmaf(v.y, scale, shift) <= 0.f) m1 |= 1u << (4*j - 31);
        if (fmaf(v.z, scale, shift) <= 0.f) m1 |= 1u << (4*j - 30);
        if (fmaf(v.w, scale, shift) <= 0.f) m1 |= 1u << (4*j - 29);
    }
    unsigned c = (unsigned)(__popc(m0) + __popc(m1));

    // block exclusive scan of c (8 warps)
    unsigned incl = c;
#pragma unroll
    for (int off = 1; off < 32; off <<= 1) {
        unsigned n = __shfl_up_sync(0xffffffffu, incl, off);
        if (lane >= off) incl += n;
    }
    __shared__ unsigned wsum[8];
    __shared__ unsigned wexcl[8];
    __shared__ unsigned total_s;
    if (lane == 31) wsum[warp] = incl;
    __syncthreads();
    if (tid < 8) {
        unsigned v = wsum[tid];
        unsigned e = 0;
        for (int j = 0; j < 8; j++) { if (j < tid) e += wsum[j]; }
        wexcl[tid] = e;
        if (tid == 7) total_s = e + v;
    }
    __syncthreads();
    const unsigned T = total_s;

    if (T >= (unsigned)TOPN) {
        unsigned r = wexcl[warp] + (incl - c);
        if (r < (unsigned)TOPN) {
            unsigned base_i = (unsigned)tid * 64u;
#pragma unroll
            for (int j = 0; j < 32; j++) {
                if (m0 & (1u << j)) {
                    if (r < (unsigned)TOPN) g_idx[b * TOPN + r] = base_i + j;
                    r++;
                }
            }
#pragma unroll
            for (int j = 0; j < 32; j++) {
                if (m1 & (1u << j)) {
                    if (r < (unsigned)TOPN) g_idx[b * TOPN + r] = base_i + 32 + j;
                    r++;
                }
            }
        }
        return;
    }

    // ===== slow path (T < TOPN): obviously-correct iterative min selection =====
    // Build stable keys, then TOPN rounds of global argmin. Never taken for
    // N(0,1) data; correctness-only.
    unsigned long long* kb = g_keys + (size_t)b * SEQ;
    for (int i = tid; i < SEQ; i += K1_THREADS) {
        float r = fmaxf(0.f, fmaf(sc[i], scale, shift));
        kb[i] = ((unsigned long long)__float_as_uint(r) << 14) | (unsigned)i;
    }
    __syncthreads();
    __shared__ unsigned long long mv[K1_THREADS];
    __shared__ int mp[K1_THREADS];
    for (int r = 0; r < TOPN; r++) {
        unsigned long long best = ~0ULL; int bp = 0;
        for (int i = tid; i < SEQ; i += K1_THREADS) {
            unsigned long long k = kb[i];
            if (k < best) { best = k; bp = i; }
        }
        mv[tid] = best; mp[tid] = bp;
        __syncthreads();
        for (int off = K1_THREADS / 2; off > 0; off >>= 1) {
            if (tid < off && mv[tid + off] < mv[tid]) {
                mv[tid] = mv[tid + off]; mp[tid] = mp[tid + off];
            }
            __syncthreads();
        }
        if (tid == 0) {
            g_idx[b * TOPN + r] = (unsigned)(mv[0] & 0x3fffu);
            kb[mp[0]] = ~0ULL;
        }
        __syncthreads();
    }
}

// ---------------------------------------------------------------------------
// K3: gather rows: out[b, r, :] = x_select[b, idx[b,r], :]
// ---------------------------------------------------------------------------
__global__ __launch_bounds__(512) void gather_kernel(const float* __restrict__ xs,
                                                     float* __restrict__ out) {
    int rid  = blockIdx.x * 8 + (threadIdx.x >> 6);   // 0 .. BATCH*TOPN-1
    int lane = threadIdx.x & 63;
    int b    = rid >> 11;                              // TOPN == 2048
    unsigned idx = g_idx[rid];
    const float4* src = (const float4*)(xs + ((size_t)b * SEQ + idx) * CH);
    float4* dst = (float4*)(out + (size_t)rid * CH);
    __stcs(dst + lane, __ldcs(src + lane));
}

// ---------------------------------------------------------------------------
extern "C" void kernel_launch(void* const* d_in, const int* in_sizes, int n_in,
                              void* d_out, int out_size) {
    const float* x_in  = (const float*)d_in[0];
    const float* x_sel = (const float*)d_in[1];
    const float* w     = (const float*)d_in[2];
    const float* bias  = (const float*)d_in[3];
    const float* gamma = (const float*)d_in[4];
    const float* beta  = (const float*)d_in[5];
    float* out = (float*)d_out;

    score_select_kernel<<<K1_GRID, K1_THREADS>>>(x_in, w, bias, gamma, beta);
    gather_kernel<<<(BATCH * TOPN) / 8, 512>>>(x_sel, out);
}

// round 9
// speedup vs baseline: 1.0724x; 1.0724x over previous
#include <cuda_runtime.h>

static constexpr int BATCH = 8;
static constexpr int SEQ   = 16384;
static constexpr int CH    = 256;
static constexpr int TOPN  = 2048;
static constexpr int ROWS  = BATCH * SEQ;     // 131072
static constexpr int QUADS = ROWS / 4;        // 32768

static constexpr int K1_GRID    = 444;        // 148 SMs * 3 resident CTAs
static constexpr int K1_THREADS = 256;        // 8 warps
static constexpr int K1_WARPS_TOTAL = K1_GRID * (K1_THREADS / 32);  // 3552

__device__ float g_score[ROWS];
__device__ float g_psum[K1_GRID];
__device__ float g_psq[K1_GRID];
__device__ unsigned g_idx[BATCH * TOPN];

// ---------------------------------------------------------------------------
// K1: persistent grid-stride. A warp covers 4 rows, 8 lanes per row
// (lane = 8*subrow + pos). 8 front-batched float4 streaming loads per thread;
// row reduce = 3-step shfl butterfly (4 rows simultaneously in one register).
// ---------------------------------------------------------------------------
__global__ __launch_bounds__(K1_THREADS, 3) void score_kernel(const float* __restrict__ x,
                                                              const float* __restrict__ w,
                                                              const float* __restrict__ bias) {
    const int warp   = threadIdx.x >> 5;
    const int lane   = threadIdx.x & 31;
    const int subrow = lane >> 3;
    const int pos    = lane & 7;
    const int gw     = blockIdx.x * (K1_THREADS / 32) + warp;

    const float4* wv = (const float4*)w;
    float4 W[8];
#pragma unroll
    for (int j = 0; j < 8; j++) W[j] = wv[pos + 8*j];
    const float bb = bias[0];

    float S = 0.f, Q = 0.f;

    for (int quad = gw; quad < QUADS; quad += K1_WARPS_TOTAL) {
        const size_t row = (size_t)quad * 4 + subrow;
        const float4* xb = (const float4*)(x + row * CH);

        float4 v[8];
#pragma unroll
        for (int j = 0; j < 8; j++) v[j] = __ldcs(xb + pos + 8*j);

        float d = 0.f;
#pragma unroll
        for (int j = 0; j < 8; j++)
            d += v[j].x*W[j].x + v[j].y*W[j].y + v[j].z*W[j].z + v[j].w*W[j].w;

        d += __shfl_xor_sync(0xffffffffu, d, 4);
        d += __shfl_xor_sync(0xffffffffu, d, 2);
        d += __shfl_xor_sync(0xffffffffu, d, 1);

        if (pos == 0) {
            float c = d + bb;
            __stcs(&g_score[row], c);
            S += c;
            Q += c * c;
        }
    }

#pragma unroll
    for (int off = 16; off > 0; off >>= 1) {
        S += __shfl_xor_sync(0xffffffffu, S, off);
        Q += __shfl_xor_sync(0xffffffffu, Q, off);
    }
    __shared__ float ws[K1_THREADS / 32], wq[K1_THREADS / 32];
    if (lane == 0) { ws[warp] = S; wq[warp] = Q; }
    __syncthreads();
    if (threadIdx.x < 32) {
        float s = (threadIdx.x < K1_THREADS / 32) ? ws[threadIdx.x] : 0.f;
        float q = (threadIdx.x < K1_THREADS / 32) ? wq[threadIdx.x] : 0.f;
#pragma unroll
        for (int off = 4; off > 0; off >>= 1) {
            s += __shfl_xor_sync(0xffffffffu, s, off);
            q += __shfl_xor_sync(0xffffffffu, q, off);
        }
        if (threadIdx.x == 0) { g_psum[blockIdx.x] = s; g_psq[blockIdx.x] = q; }
    }
}

// ---------------------------------------------------------------------------
// Bitonic helper for the (practically never taken) slow path
// ---------------------------------------------------------------------------
__device__ __forceinline__ unsigned long long cex_shfl(unsigned long long E,
                                                       int i, int j, int k) {
    unsigned long long P = __shfl_xor_sync(0xffffffffu, E, j);
    bool takeMin = (((i & j) == 0) == ((i & k) == 0));
    if (takeMin ? (P < E) : (P > E)) E = P;
    return E;
}

// ---------------------------------------------------------------------------
// K2: one CTA per batch. Fast path: ReLU zeros (normalized <= 0) are first
// in stable ascending argsort, in index order -> stream compaction of the
// first TOPN qualifying indices. Slow path: radix-select + bitonic.
// ---------------------------------------------------------------------------
__global__ __launch_bounds__(1024) void select_kernel(const float* __restrict__ gamma,
                                                      const float* __restrict__ beta) {
    extern __shared__ unsigned long long dyn[];   // slow path only
    unsigned long long* keys = dyn;               // SEQ
    unsigned long long* sel  = dyn + SEQ;         // TOPN

    __shared__ float red1[512], red2[512];
    __shared__ unsigned warpsum[32];
    __shared__ unsigned warpexcl[32];
    __shared__ unsigned total_s;

    const int tid  = threadIdx.x;
    const int lane = tid & 31;
    const int warp = tid >> 5;
    const int b    = blockIdx.x;

    if (tid < 512) {
        float S = (tid < K1_GRID) ? g_psum[tid] : 0.f;
        float Q = (tid < K1_GRID) ? g_psq[tid]  : 0.f;
        red1[tid] = S; red2[tid] = Q;
    }
    __syncthreads();
    for (int off = 256; off > 0; off >>= 1) {
        if (tid < off) { red1[tid] += red1[tid + off]; red2[tid] += red2[tid + off]; }
        __syncthreads();
    }
    float mean = red1[0] / (float)ROWS;
    float var  = red2[0] / (float)ROWS - mean * mean;
    if (var < 0.f) var = 0.f;
    float scale = rsqrtf(var + 1e-5f) * gamma[0];
    float shift = beta[0] - mean * scale;

    const float* sc = g_score + (size_t)b * SEQ;
    const float4* p4 = (const float4*)(sc + tid * 16);
    unsigned mask16 = 0;
#pragma unroll
    for (int j = 0; j < 4; j++) {
        float4 v = p4[j];
        if (fmaf(v.x, scale, shift) <= 0.f) mask16 |= 1u << (4*j + 0);
        if (fmaf(v.y, scale, shift) <= 0.f) mask16 |= 1u << (4*j + 1);
        if (fmaf(v.z, scale, shift) <= 0.f) mask16 |= 1u << (4*j + 2);
        if (fmaf(v.w, scale, shift) <= 0.f) mask16 |= 1u << (4*j + 3);
    }
    unsigned c = (unsigned)__popc(mask16);

    unsigned incl = c;
#pragma unroll
    for (int off = 1; off < 32; off <<= 1) {
        unsigned n = __shfl_up_sync(0xffffffffu, incl, off);
        if (lane >= off) incl += n;
    }
    if (lane == 31) warpsum[warp] = incl;
    __syncthreads();
    if (tid < 32) {
        unsigned wv = warpsum[tid];
        unsigned wincl = wv;
#pragma unroll
        for (int off = 1; off < 32; off <<= 1) {
            unsigned n = __shfl_up_sync(0xffffffffu, wincl, off);
            if (tid >= off) wincl += n;
        }
        warpexcl[tid] = wincl - wv;
        if (tid == 31) total_s = wincl;
    }
    __syncthreads();
    unsigned T = total_s;

    if (T >= (unsigned)TOPN) {
        unsigned r = warpexcl[warp] + (incl - c);
        if (r < (unsigned)TOPN) {
            unsigned base_i = (unsigned)tid * 16u;
#pragma unroll
            for (int j = 0; j < 16; j++) {
                if (mask16 & (1u << j)) {
                    if (r < (unsigned)TOPN) g_idx[b * TOPN + r] = base_i + j;
                    r++;
                }
            }
        }
        return;
    }

    // ===== slow path (practically unreachable) =====
    __shared__ unsigned hist[256];
    __shared__ unsigned long long prefix_s;
    __shared__ int k_s;
    __shared__ unsigned cnt_s;

    for (int i = tid; i < SEQ; i += 1024) {
        float r = fmaxf(0.f, fmaf(sc[i], scale, shift));
        keys[i] = ((unsigned long long)__float_as_uint(r) << 14) | (unsigned)i;
    }
    if (tid == 0) { prefix_s = 0ULL; k_s = TOPN - 1; cnt_s = 0u; }
    __syncthreads();

    unsigned long long prefix = 0ULL;
#pragma unroll
    for (int d = 5; d >= 0; --d) {
        for (int i = tid; i < 256; i += 1024) hist[i] = 0u;
        __syncthreads();
        const int sh = d * 8;
        const unsigned long long pmask = (d == 5) ? 0ULL : (~0ULL << (sh + 8));
        for (int i = tid; i < SEQ; i += 1024) {
            unsigned long long key = keys[i];
            bool pr = ((key & pmask) == prefix);
            unsigned active = __ballot_sync(0xffffffffu, pr);
            if (pr) {
                unsigned bin = (unsigned)(key >> sh) & 255u;
                unsigned peers = __match_any_sync(active, bin);
                if (lane == __ffs(peers) - 1)
                    atomicAdd(&hist[bin], __popc(peers));
            }
        }
        __syncthreads();
        if (tid < 32) {
            int k = k_s;
            unsigned v[8]; unsigned tot = 0u;
#pragma unroll
            for (int j = 0; j < 8; j++) { v[j] = hist[tid*8 + j]; tot += v[j]; }
            unsigned ex = tot;
#pragma unroll
            for (int off = 1; off < 32; off <<= 1) {
                unsigned n = __shfl_up_sync(0xffffffffu, ex, off);
                if (tid >= off) ex += n;
            }
            ex -= tot;
            if ((unsigned)k >= ex && (unsigned)k < ex + tot) {
                unsigned kk = (unsigned)k - ex;
                int bin = tid * 8;
#pragma unroll
                for (int j = 0; j < 8; j++) {
                    if (kk < v[j]) { bin = tid*8 + j; break; }
                    kk -= v[j];
                }
                prefix_s = prefix | ((unsigned long long)bin << sh);
                k_s = (int)kk;
            }
        }
        __syncthreads();
        prefix = prefix_s;
    }
    const unsigned long long cutoff = prefix;

    for (int i = tid; i < SEQ; i += 1024) {
        unsigned long long key = keys[i];
        bool pr = (key <= cutoff);
        unsigned m = __ballot_sync(0xffffffffu, pr);
        if (pr) {
            int leader = __ffs(m) - 1;
            unsigned base;
            if (lane == leader) base = atomicAdd(&cnt_s, (unsigned)__popc(m));
            base = __shfl_sync(m, base, leader);
            sel[base + __popc(m & ((1u << lane) - 1u))] = key;
        }
    }
    __syncthreads();

    unsigned long long E0 = sel[tid];
    unsigned long long E1 = sel[tid + 1024];
#pragma unroll
    for (int k = 2; k <= 32; k <<= 1)
#pragma unroll
        for (int j = k >> 1; j >= 1; j >>= 1) {
            E0 = cex_shfl(E0, tid, j, k);
            E1 = cex_shfl(E1, tid + 1024, j, k);
        }
#pragma unroll
    for (int k = 64; k <= 1024; k <<= 1) {
        __syncthreads();
        sel[tid] = E0; sel[tid + 1024] = E1;
        __syncthreads();
        for (int j = k >> 1; j >= 32; j >>= 1) {
            int idx = ((tid & ~(j - 1)) << 1) | (tid & (j - 1));
            int l = idx | j;
            unsigned long long a = sel[idx], cc = sel[l];
            bool asc = ((idx & k) == 0);
            if ((a > cc) == asc) { sel[idx] = cc; sel[l] = a; }
            __syncthreads();
        }
        E0 = sel[tid]; E1 = sel[tid + 1024];
#pragma unroll
        for (int j = 16; j >= 1; j >>= 1) {
            E0 = cex_shfl(E0, tid, j, k);
            E1 = cex_shfl(E1, tid + 1024, j, k);
        }
    }
    {
        const int k = 2048;
        if (E0 > E1) { unsigned long long t = E0; E0 = E1; E1 = t; }
        __syncthreads();
        sel[tid] = E0; sel[tid + 1024] = E1;
        __syncthreads();
        for (int j = 512; j >= 32; j >>= 1) {
            int idx = ((tid & ~(j - 1)) << 1) | (tid & (j - 1));
            int l = idx | j;
            unsigned long long a = sel[idx], cc = sel[l];
            if (a > cc) { sel[idx] = cc; sel[l] = a; }
            __syncthreads();
        }
        E0 = sel[tid]; E1 = sel[tid + 1024];
#pragma unroll
        for (int j = 16; j >= 1; j >>= 1) {
            E0 = cex_shfl(E0, tid, j, k);
            E1 = cex_shfl(E1, tid + 1024, j, k);
        }
    }
    g_idx[b * TOPN + tid]        = (unsigned)(E0 & 0x3fffu);
    g_idx[b * TOPN + tid + 1024] = (unsigned)(E1 & 0x3fffu);
}

// ---------------------------------------------------------------------------
// K3: gather rows: out[b, r, :] = x_select[b, idx[b,r], :]
// 512 threads / 32 rows per block. Row indices staged in smem (one coalesced
// read per block); 16 threads per row, each moving 4 front-batched float4s
// (MLP=4, dependent idx->data chain paid once per block).
// ---------------------------------------------------------------------------
__global__ __launch_bounds__(512) void gather_kernel(const float* __restrict__ xs,
                                                     float* __restrict__ out) {
    __shared__ unsigned sidx[32];
    const int t = threadIdx.x;
    const int row0 = blockIdx.x * 32;            // first output row of block
    if (t < 32) sidx[t] = g_idx[row0 + t];
    __syncthreads();

    const int lrow = t >> 4;                     // 0..31
    const int pos  = t & 15;                     // 0..15
    const int rid  = row0 + lrow;
    const int b    = rid >> 11;                  // TOPN == 2048
    const unsigned idx = sidx[lrow];

    const float4* src = (const float4*)(xs + ((size_t)b * SEQ + idx) * CH);
    float4* dst = (float4*)(out + (size_t)rid * CH);

    float4 v0 = __ldcs(src + pos);
    float4 v1 = __ldcs(src + 16 + pos);
    float4 v2 = __ldcs(src + 32 + pos);
    float4 v3 = __ldcs(src + 48 + pos);
    __stcs(dst + pos,      v0);
    __stcs(dst + 16 + pos, v1);
    __stcs(dst + 32 + pos, v2);
    __stcs(dst + 48 + pos, v3);
}

// ---------------------------------------------------------------------------
extern "C" void kernel_launch(void* const* d_in, const int* in_sizes, int n_in,
                              void* d_out, int out_size) {
    const float* x_in  = (const float*)d_in[0];
    const float* x_sel = (const float*)d_in[1];
    const float* w     = (const float*)d_in[2];
    const float* bias  = (const float*)d_in[3];
    const float* gamma = (const float*)d_in[4];
    const float* beta  = (const float*)d_in[5];
    float* out = (float*)d_out;

    const int sel_smem = (SEQ + TOPN) * (int)sizeof(unsigned long long);  // 147456
    cudaFuncSetAttribute(select_kernel,
                         cudaFuncAttributeMaxDynamicSharedMemorySize, sel_smem);

    score_kernel<<<K1_GRID, K1_THREADS>>>(x_in, w, bias);
    select_kernel<<<BATCH, 1024, sel_smem>>>(gamma, beta);
    gather_kernel<<<(BATCH * TOPN) / 32, 512>>>(x_sel, out);
}

// round 11
// speedup vs baseline: 1.1164x; 1.0411x over previous
#include <cuda_runtime.h>

static constexpr int BATCH = 8;
static constexpr int SEQ   = 16384;
static constexpr int CH    = 256;
static constexpr int TOPN  = 2048;
static constexpr int ROWS  = BATCH * SEQ;     // 131072
static constexpr int QUADS = ROWS / 4;        // 32768

static constexpr int K1_GRID    = 444;        // 148 SMs * 3 resident CTAs
static constexpr int K1_THREADS = 256;        // 8 warps
static constexpr int K1_WARPS_TOTAL = K1_GRID * (K1_THREADS / 32);  // 3552

__device__ float g_score[ROWS];
__device__ float g_psum[K1_GRID];
__device__ float g_psq[K1_GRID];
__device__ unsigned g_idx[BATCH * TOPN];
__device__ unsigned long long g_keys[ROWS];   // slow-path scratch (global, NOT smem)

// ---------------------------------------------------------------------------
// K1: persistent grid-stride. A warp covers 4 rows, 8 lanes per row
// (lane = 8*subrow + pos). 8 front-batched float4 streaming loads per thread;
// row reduce = 3-step shfl butterfly (4 rows simultaneously in one register).
// ---------------------------------------------------------------------------
__global__ __launch_bounds__(K1_THREADS, 3) void score_kernel(const float* __restrict__ x,
                                                              const float* __restrict__ w,
                                                              const float* __restrict__ bias) {
    const int warp   = threadIdx.x >> 5;
    const int lane   = threadIdx.x & 31;
    const int subrow = lane >> 3;
    const int pos    = lane & 7;
    const int gw     = blockIdx.x * (K1_THREADS / 32) + warp;

    const float4* wv = (const float4*)w;
    float4 W[8];
#pragma unroll
    for (int j = 0; j < 8; j++) W[j] = wv[pos + 8*j];
    const float bb = bias[0];

    float S = 0.f, Q = 0.f;

    for (int quad = gw; quad < QUADS; quad += K1_WARPS_TOTAL) {
        const size_t row = (size_t)quad * 4 + subrow;
        const float4* xb = (const float4*)(x + row * CH);

        float4 v[8];
#pragma unroll
        for (int j = 0; j < 8; j++) v[j] = __ldcs(xb + pos + 8*j);

        float d = 0.f;
#pragma unroll
        for (int j = 0; j < 8; j++)
            d += v[j].x*W[j].x + v[j].y*W[j].y + v[j].z*W[j].z + v[j].w*W[j].w;

        d += __shfl_xor_sync(0xffffffffu, d, 4);
        d += __shfl_xor_sync(0xffffffffu, d, 2);
        d += __shfl_xor_sync(0xffffffffu, d, 1);

        if (pos == 0) {
            float c = d + bb;
            __stcs(&g_score[row], c);
            S += c;
            Q += c * c;
        }
    }

#pragma unroll
    for (int off = 16; off > 0; off >>= 1) {
        S += __shfl_xor_sync(0xffffffffu, S, off);
        Q += __shfl_xor_sync(0xffffffffu, Q, off);
    }
    __shared__ float ws[K1_THREADS / 32], wq[K1_THREADS / 32];
    if (lane == 0) { ws[warp] = S; wq[warp] = Q; }
    __syncthreads();
    if (threadIdx.x < 32) {
        float s = (threadIdx.x < K1_THREADS / 32) ? ws[threadIdx.x] : 0.f;
        float q = (threadIdx.x < K1_THREADS / 32) ? wq[threadIdx.x] : 0.f;
#pragma unroll
        for (int off = 4; off > 0; off >>= 1) {
            s += __shfl_xor_sync(0xffffffffu, s, off);
            q += __shfl_xor_sync(0xffffffffu, q, off);
        }
        if (threadIdx.x == 0) { g_psum[blockIdx.x] = s; g_psq[blockIdx.x] = q; }
    }
}

// ---------------------------------------------------------------------------
// K2: one CTA per batch. Fast path: ReLU zeros (normalized <= 0) are first
// in stable ascending argsort, in index order -> stream compaction of the
// first TOPN qualifying indices. Slow path (T < TOPN, practically
// unreachable): obviously-correct iterative global argmin on 46-bit stable
// keys in GLOBAL scratch -> select kernel uses only small static smem, so
// no smem-carveout reconfiguration between kernels.
// ---------------------------------------------------------------------------
__global__ __launch_bounds__(1024) void select_kernel(const float* __restrict__ gamma,
                                                      const float* __restrict__ beta) {
    __shared__ float red1[512], red2[512];
    __shared__ unsigned warpsum[32];
    __shared__ unsigned warpexcl[32];
    __shared__ unsigned total_s;

    const int tid  = threadIdx.x;
    const int lane = tid & 31;
    const int warp = tid >> 5;
    const int b    = blockIdx.x;

    // --- mean / var from K1 partials ---
    if (tid < 512) {
        float S = (tid < K1_GRID) ? g_psum[tid] : 0.f;
        float Q = (tid < K1_GRID) ? g_psq[tid]  : 0.f;
        red1[tid] = S; red2[tid] = Q;
    }
    __syncthreads();
    for (int off = 256; off > 0; off >>= 1) {
        if (tid < off) { red1[tid] += red1[tid + off]; red2[tid] += red2[tid + off]; }
        __syncthreads();
    }
    float mean = red1[0] / (float)ROWS;
    float var  = red2[0] / (float)ROWS - mean * mean;
    if (var < 0.f) var = 0.f;
    float scale = rsqrtf(var + 1e-5f) * gamma[0];
    float shift = beta[0] - mean * scale;

    // --- fast path: stable compaction of normalized <= 0 ---
    const float* sc = g_score + (size_t)b * SEQ;
    const float4* p4 = (const float4*)(sc + tid * 16);
    unsigned mask16 = 0;
#pragma unroll
    for (int j = 0; j < 4; j++) {
        float4 v = p4[j];
        if (fmaf(v.x, scale, shift) <= 0.f) mask16 |= 1u << (4*j + 0);
        if (fmaf(v.y, scale, shift) <= 0.f) mask16 |= 1u << (4*j + 1);
        if (fmaf(v.z, scale, shift) <= 0.f) mask16 |= 1u << (4*j + 2);
        if (fmaf(v.w, scale, shift) <= 0.f) mask16 |= 1u << (4*j + 3);
    }
    unsigned c = (unsigned)__popc(mask16);

    unsigned incl = c;
#pragma unroll
    for (int off = 1; off < 32; off <<= 1) {
        unsigned n = __shfl_up_sync(0xffffffffu, incl, off);
        if (lane >= off) incl += n;
    }
    if (lane == 31) warpsum[warp] = incl;
    __syncthreads();
    if (tid < 32) {
        unsigned wv = warpsum[tid];
        unsigned wincl = wv;
#pragma unroll
        for (int off = 1; off < 32; off <<= 1) {
            unsigned n = __shfl_up_sync(0xffffffffu, wincl, off);
            if (tid >= off) wincl += n;
        }
        warpexcl[tid] = wincl - wv;
        if (tid == 31) total_s = wincl;
    }
    __syncthreads();
    unsigned T = total_s;

    if (T >= (unsigned)TOPN) {
        unsigned r = warpexcl[warp] + (incl - c);
        if (r < (unsigned)TOPN) {
            unsigned base_i = (unsigned)tid * 16u;
#pragma unroll
            for (int j = 0; j < 16; j++) {
                if (mask16 & (1u << j)) {
                    if (r < (unsigned)TOPN) g_idx[b * TOPN + r] = base_i + j;
                    r++;
                }
            }
        }
        return;
    }

    // ===== slow path: iterative global argmin (correctness-only) =====
    unsigned long long* kb = g_keys + (size_t)b * SEQ;
    for (int i = tid; i < SEQ; i += 1024) {
        float r = fmaxf(0.f, fmaf(sc[i], scale, shift));
        kb[i] = ((unsigned long long)__float_as_uint(r) << 14) | (unsigned)i;
    }
    __syncthreads();
    __shared__ unsigned long long mv[1024];
    __shared__ int mp[1024];
    for (int r = 0; r < TOPN; r++) {
        unsigned long long best = ~0ULL; int bp = 0;
        for (int i = tid; i < SEQ; i += 1024) {
            unsigned long long k = kb[i];
            if (k < best) { best = k; bp = i; }
        }
        mv[tid] = best; mp[tid] = bp;
        __syncthreads();
        for (int off = 512; off > 0; off >>= 1) {
            if (tid < off && mv[tid + off] < mv[tid]) {
                mv[tid] = mv[tid + off]; mp[tid] = mp[tid + off];
            }
            __syncthreads();
        }
        if (tid == 0) {
            g_idx[b * TOPN + r] = (unsigned)(mv[0] & 0x3fffu);
            kb[mp[0]] = ~0ULL;
        }
        __syncthreads();
    }
}

// ---------------------------------------------------------------------------
// K3: gather rows: out[b, r, :] = x_select[b, idx[b,r], :]
// 512 threads / 64 rows per block. Row indices staged in smem; 8 threads per
// row, each moving 8 front-batched float4s (MLP=8).
// ---------------------------------------------------------------------------
__global__ __launch_bounds__(512) void gather_kernel(const float* __restrict__ xs,
                                                     float* __restrict__ out) {
    __shared__ unsigned sidx[64];
    const int t = threadIdx.x;
    const int row0 = blockIdx.x * 64;            // first output row of block
    if (t < 64) sidx[t] = g_idx[row0 + t];
    __syncthreads();

    const int lrow = t >> 3;                     // 0..63
    const int pos  = t & 7;                      // 0..7
    const int rid  = row0 + lrow;
    const int b    = rid >> 11;                  // TOPN == 2048
    const unsigned idx = sidx[lrow];

    const float4* src = (const float4*)(xs + ((size_t)b * SEQ + idx) * CH);
    float4* dst = (float4*)(out + (size_t)rid * CH);

    float4 v[8];
#pragma unroll
    for (int j = 0; j < 8; j++) v[j] = __ldcs(src + pos + 8*j);
#pragma unroll
    for (int j = 0; j < 8; j++) __stcs(dst + pos + 8*j, v[j]);
}

// ---------------------------------------------------------------------------
extern "C" void kernel_launch(void* const* d_in, const int* in_sizes, int n_in,
                              void* d_out, int out_size) {
    const float* x_in  = (const float*)d_in[0];
    const float* x_sel = (const float*)d_in[1];
    const float* w     = (const float*)d_in[2];
    const float* bias  = (const float*)d_in[3];
    const float* gamma = (const float*)d_in[4];
    const float* beta  = (const float*)d_in[5];
    float* out = (float*)d_out;

    score_kernel<<<K1_GRID, K1_THREADS>>>(x_in, w, bias);
    select_kernel<<<BATCH, 1024>>>(gamma, beta);
    gather_kernel<<<(BATCH * TOPN) / 64, 512>>>(x_sel, out);
}